// round 4
// baseline (speedup 1.0000x reference)
#include <cuda_runtime.h>
#include <cuda_fp16.h>
#include <cuda.h>
#include <cstdint>
#include <cstddef>

#define IN_F   4096
#define OUT_F  4096
#define MROWS  4096
#define RANK   32
#define KTOT   4160
#define TM     128
#define TN     128
#define TK     64
#define NKT    65
#define PSTG   4
#define STAGE_A_BYTES (TM*TK*2)          // 16 KB
#define STAGE_B_BYTES (TN*TK*2)          // 16 KB
#define STAGE_BYTES   (STAGE_A_BYTES + STAGE_B_BYTES)
#define SMEM_HDR      1024
#define SMEM_TOTAL    (SMEM_HDR + PSTG*STAGE_BYTES)   // 132096

__device__ __half g_xcat[(size_t)MROWS * KTOT];
__device__ __half g_wcat[(size_t)OUT_F * KTOT];
__device__ __half g_xs  [(size_t)MROWS * IN_F];

__device__ __forceinline__ uint32_t smem_u32(const void* p) {
    uint32_t a;
    asm("{ .reg .u64 t; cvta.to.shared.u64 t, %1; cvt.u32.u64 %0, t; }" : "=r"(a) : "l"(p));
    return a;
}

#define MBAR_INIT(addr, cnt) \
    asm volatile("mbarrier.init.shared.b64 [%0], %1;" :: "r"(addr), "r"((uint32_t)(cnt)) : "memory")
#define MBAR_EXPECT_TX(addr, b) \
    asm volatile("mbarrier.arrive.expect_tx.shared.b64 _, [%0], %1;" :: "r"(addr), "r"((uint32_t)(b)) : "memory")
#define MBAR_ARRIVE(addr) \
    asm volatile("mbarrier.arrive.shared.b64 _, [%0];" :: "r"(addr) : "memory")
#define MBAR_WAIT(addr, ph) do {                                              \
    uint32_t _m = (addr), _p = (uint32_t)(ph), _d;                            \
    asm volatile("{\n\t.reg .pred p;\n\t"                                     \
        "mbarrier.try_wait.parity.acquire.cta.shared::cta.b64 p, [%1], %2;\n\t" \
        "selp.b32 %0, 1, 0, p;\n\t}"                                          \
        : "=r"(_d) : "r"(_m), "r"(_p) : "memory");                            \
    if (!_d) {                                                                \
        asm volatile("{\n\t.reg .pred P1;\n\t"                                \
            "WL%=:\n\t"                                                       \
            "mbarrier.try_wait.parity.acquire.cta.shared::cta.b64 P1, [%0], %1, 0x989680;\n\t" \
            "@P1 bra.uni WD%=;\n\t"                                           \
            "bra.uni WL%=;\n\t"                                               \
            "WD%=:\n\t}" :: "r"(_m), "r"(_p) : "memory");                     \
    }                                                                         \
} while (0)

__device__ __forceinline__ void tma_load_2d(uint32_t smem_addr, const CUtensorMap* map,
                                            int cx, int cy, uint32_t mbar) {
    asm volatile(
        "cp.async.bulk.tensor.2d.shared::cta.global.tile.mbarrier::complete_tx::bytes "
        "[%0], [%1, {%2, %3}], [%4];"
        :: "r"(smem_addr), "l"((unsigned long long)(uintptr_t)map),
           "r"(cx), "r"(cy), "r"(mbar) : "memory");
}

__device__ __forceinline__ void ldsm_x4(uint32_t& r0, uint32_t& r1, uint32_t& r2, uint32_t& r3,
                                        uint32_t addr) {
    asm volatile("ldmatrix.sync.aligned.m8n8.x4.shared.b16 {%0,%1,%2,%3}, [%4];"
                 : "=r"(r0), "=r"(r1), "=r"(r2), "=r"(r3) : "r"(addr));
}

__device__ __forceinline__ void mma16816(float* c, const uint32_t* a, uint32_t b0, uint32_t b1) {
    asm volatile(
        "mma.sync.aligned.m16n8k16.row.col.f32.f16.f16.f32 "
        "{%0,%1,%2,%3}, {%4,%5,%6,%7}, {%8,%9}, {%0,%1,%2,%3};"
        : "+f"(c[0]), "+f"(c[1]), "+f"(c[2]), "+f"(c[3])
        : "r"(a[0]), "r"(a[1]), "r"(a[2]), "r"(a[3]), "r"(b0), "r"(b1));
}

// ---- prologue 1: w_cat = [W | lora_b | 0] fp16 ----
__global__ void build_wcat_kernel(const float* __restrict__ w,
                                  const float* __restrict__ lb,
                                  __half* __restrict__ wcat) {
    int idx = blockIdx.x * 256 + threadIdx.x;
    int o = idx / KTOT;
    int c = idx - o * KTOT;
    float v;
    if (c < IN_F)             v = w[(size_t)o * IN_F + c];
    else if (c < IN_F + RANK) v = lb[(size_t)o * RANK + (c - IN_F)];
    else                      v = 0.0f;
    wcat[idx] = __float2half(v);
}

// ---- prologue 2: smooth + exact NVFP4 fake-quant ----
__global__ void quant_x_kernel(const float* __restrict__ x,
                               const float* __restrict__ ss,
                               __half* __restrict__ xs,
                               __half* __restrict__ xcat) {
    int b = blockIdx.x * blockDim.x + threadIdx.x;   // 16-elem block index
    int row = b >> 8;
    int kb  = (b & 255) << 4;
    const float4* xp = reinterpret_cast<const float4*>(x + (size_t)row * IN_F + kb);
    const float4* sp = reinterpret_cast<const float4*>(ss + kb);
    float v[16];
#pragma unroll
    for (int i = 0; i < 4; i++) {
        float4 a = xp[i]; float4 s = sp[i];
        v[4*i+0] = a.x * s.x; v[4*i+1] = a.y * s.y;
        v[4*i+2] = a.z * s.z; v[4*i+3] = a.w * s.w;
    }
    float amax = 0.0f;
#pragma unroll
    for (int i = 0; i < 16; i++) amax = fmaxf(amax, fabsf(v[i]));
    amax = fmaxf(amax, 1e-12f);
    float scale = amax / 6.0f;
    __align__(16) __half h_s[16];
    __align__(16) __half h_q[16];
#pragma unroll
    for (int i = 0; i < 16; i++) {
        h_s[i] = __float2half(v[i]);
        float an = fabsf(v[i]) / scale;
        float lvl;
        if      (an <= 0.25f) lvl = 0.0f;   // <= : tie -> lower level (argmin-first)
        else if (an <= 0.75f) lvl = 0.5f;
        else if (an <= 1.25f) lvl = 1.0f;
        else if (an <= 1.75f) lvl = 1.5f;
        else if (an <= 2.5f)  lvl = 2.0f;
        else if (an <= 3.5f)  lvl = 3.0f;
        else if (an <= 5.0f)  lvl = 4.0f;
        else                  lvl = 6.0f;
        h_q[i] = __float2half(copysignf(lvl * scale, v[i]));
    }
    uint4* d1 = reinterpret_cast<uint4*>(xs + (size_t)row * IN_F + kb);
    d1[0] = reinterpret_cast<uint4*>(h_s)[0];
    d1[1] = reinterpret_cast<uint4*>(h_s)[1];
    uint4* d2 = reinterpret_cast<uint4*>(xcat + (size_t)row * KTOT + kb);
    d2[0] = reinterpret_cast<uint4*>(h_q)[0];
    d2[1] = reinterpret_cast<uint4*>(h_q)[1];
}

__global__ void zero_tail_kernel(__half* __restrict__ xcat) {
    int idx = blockIdx.x * blockDim.x + threadIdx.x;  // 4096*4 uint4
    int row = idx >> 2;
    int j   = idx & 3;
    reinterpret_cast<uint4*>(xcat + (size_t)row * KTOT + IN_F + RANK)[j] = make_uint4(0,0,0,0);
}

// ---- prologue 3: t = x_s @ lora_a^T -> x_cat cols [4096,4128) ----
__global__ void lora_t_kernel(const __half* __restrict__ xs,
                              const float* __restrict__ la,
                              __half* __restrict__ xcat) {
    __shared__ float  sa[RANK][129];
    __shared__ __half sx[16][128];
    int row0 = blockIdx.x * 16;
    int tid  = threadIdx.x;
    int lane = tid & 31;
    int warp = tid >> 5;
    float acc0 = 0.0f, acc1 = 0.0f;
    for (int k0 = 0; k0 < IN_F; k0 += 128) {
        __syncthreads();
        for (int idx = tid; idx < RANK * 128; idx += 256) {
            int r = idx >> 7, kk = idx & 127;
            sa[r][kk] = la[(size_t)r * IN_F + k0 + kk];
        }
        for (int idx = tid; idx < 16 * 64; idx += 256) {
            int r = idx >> 6, kk2 = idx & 63;
            reinterpret_cast<uint32_t*>(&sx[r][0])[kk2] =
                reinterpret_cast<const uint32_t*>(xs + (size_t)(row0 + r) * IN_F + k0)[kk2];
        }
        __syncthreads();
        int r0 = warp * 2;
#pragma unroll 8
        for (int kk = 0; kk < 128; kk++) {
            float av = sa[lane][kk];
            acc0 += __half2float(sx[r0][kk])     * av;
            acc1 += __half2float(sx[r0 + 1][kk]) * av;
        }
    }
    xcat[(size_t)(row0 + warp * 2)     * KTOT + IN_F + lane] = __float2half(acc0);
    xcat[(size_t)(row0 + warp * 2 + 1) * KTOT + IN_F + lane] = __float2half(acc1);
}

// ---- main GEMM: 128x128 CTA tile, warp tile 64x64, mma.sync m16n8k16 ----
#define OFF_FULL(s)  (16u + 8u * (s))
#define OFF_EMPTY(s) (64u + 8u * (s))
#define OFF_A(s)     (SMEM_HDR + (s) * STAGE_BYTES)
#define OFF_B(s)     (OFF_A(s) + STAGE_A_BYTES)

__global__ void __launch_bounds__(160, 1)
gemm_kernel(const __grid_constant__ CUtensorMap tma_a,
            const __grid_constant__ CUtensorMap tma_b,
            const float* __restrict__ bias,
            float* __restrict__ out) {
    extern __shared__ __align__(1024) char smem_buf[];
    uint32_t sbase = smem_u32(smem_buf);
    int tid  = threadIdx.x;
    int warp = tid >> 5;
    int lane = tid & 31;
    int m0 = blockIdx.x * TM;
    int n0 = blockIdx.y * TN;

    if (tid == 0) {
        for (int s = 0; s < PSTG; s++) {
            MBAR_INIT(sbase + OFF_FULL(s), 1);
            MBAR_INIT(sbase + OFF_EMPTY(s), 128);
        }
    }
    __syncthreads();

    if (warp == 4) {
        // ------------- TMA producer (lane 0) -------------
        if (lane == 0) {
            int s = 0;
            for (int kt = 0; kt < NKT; kt++) {
                if (kt >= PSTG) MBAR_WAIT(sbase + OFF_EMPTY(s), ((kt - PSTG) / PSTG) & 1);
                MBAR_EXPECT_TX(sbase + OFF_FULL(s), STAGE_BYTES);
                tma_load_2d(sbase + OFF_A(s), &tma_a, kt * TK, m0, sbase + OFF_FULL(s));
                tma_load_2d(sbase + OFF_B(s), &tma_b, kt * TK, n0, sbase + OFF_FULL(s));
                if (++s == PSTG) s = 0;
            }
        }
        return;
    }

    // ------------- consumers: 4 warps, 2x2 grid, 64x64 each -------------
    int wm = (warp >> 1) * 64;          // warp m offset in tile
    int wn = (warp & 1) * 64;           // warp n offset in tile

    // ldmatrix row (fixed per lane across k): row = base + (lane&7) + ((lane>>3)&1)*8
    int lrow = (lane & 7) + ((lane >> 3) & 1) * 8;
    int lhi  = (lane >> 4) & 1;         // selects k-chunk lo/hi 16B within a kstep

    // Precompute per-lane row byte offsets + swizzle keys
    uint32_t arow[4], asw[4], brow[4], bsw[4];
#pragma unroll
    for (int i = 0; i < 4; i++) {
        int ra = wm + i * 16 + lrow;
        arow[i] = (uint32_t)ra * 128u; asw[i] = (uint32_t)(ra & 7);
        int rb = wn + i * 16 + lrow;
        brow[i] = (uint32_t)rb * 128u; bsw[i] = (uint32_t)(rb & 7);
    }

    float acc[4][8][4];
#pragma unroll
    for (int i = 0; i < 4; i++)
#pragma unroll
        for (int j = 0; j < 8; j++)
#pragma unroll
            for (int q = 0; q < 4; q++) acc[i][j][q] = 0.0f;

    int s = 0;
    for (int kt = 0; kt < NKT; kt++) {
        int ph = (kt / PSTG) & 1;
        MBAR_WAIT(sbase + OFF_FULL(s), ph);
        uint32_t aS = sbase + OFF_A(s);
        uint32_t bS = sbase + OFF_B(s);
#pragma unroll
        for (int ks = 0; ks < 4; ks++) {
            uint32_t chunk = (uint32_t)(ks * 2 + lhi);
            uint32_t a[4][4];
            uint32_t bf[8][2];
#pragma unroll
            for (int mi = 0; mi < 4; mi++)
                ldsm_x4(a[mi][0], a[mi][1], a[mi][2], a[mi][3],
                        aS + arow[mi] + (((chunk ^ asw[mi]) & 7u) << 4));
#pragma unroll
            for (int nj = 0; nj < 4; nj++) {
                uint32_t r0, r1, r2, r3;
                ldsm_x4(r0, r1, r2, r3,
                        bS + brow[nj] + (((chunk ^ bsw[nj]) & 7u) << 4));
                bf[2*nj][0] = r0; bf[2*nj][1] = r2;       // n rows 0-7 of the 16
                bf[2*nj+1][0] = r1; bf[2*nj+1][1] = r3;   // n rows 8-15
            }
#pragma unroll
            for (int mi = 0; mi < 4; mi++)
#pragma unroll
                for (int ni = 0; ni < 8; ni++)
                    mma16816(acc[mi][ni], a[mi], bf[ni][0], bf[ni][1]);
        }
        MBAR_ARRIVE(sbase + OFF_EMPTY(s));
        if (++s == PSTG) s = 0;
    }

    // ------------- epilogue: bias + store -------------
    int crow = lane >> 2;
    int ccol = (lane & 3) * 2;
    float2 bfrag[8];
#pragma unroll
    for (int ni = 0; ni < 8; ni++)
        bfrag[ni] = __ldg(reinterpret_cast<const float2*>(bias + n0 + wn + ni * 8 + ccol));
#pragma unroll
    for (int mi = 0; mi < 4; mi++) {
        int m_lo = m0 + wm + mi * 16 + crow;
#pragma unroll
        for (int ni = 0; ni < 8; ni++) {
            int col = n0 + wn + ni * 8 + ccol;
            float2 v0, v1;
            v0.x = acc[mi][ni][0] + bfrag[ni].x;
            v0.y = acc[mi][ni][1] + bfrag[ni].y;
            v1.x = acc[mi][ni][2] + bfrag[ni].x;
            v1.y = acc[mi][ni][3] + bfrag[ni].y;
            *reinterpret_cast<float2*>(out + (size_t)m_lo * OUT_F + col) = v0;
            *reinterpret_cast<float2*>(out + (size_t)(m_lo + 8) * OUT_F + col) = v1;
        }
    }
}

typedef CUresult (*tmap_fn_t)(CUtensorMap*, CUtensorMapDataType, cuuint32_t, void*,
                              const cuuint64_t*, const cuuint64_t*, const cuuint32_t*,
                              const cuuint32_t*, CUtensorMapInterleave, CUtensorMapSwizzle,
                              CUtensorMapL2promotion, CUtensorMapFloatOOBfill);

extern "C" void kernel_launch(void* const* d_in, const int* in_sizes, int n_in,
                              void* d_out, int out_size) {
    (void)in_sizes; (void)n_in; (void)out_size;
    const float* x      = (const float*)d_in[0];
    const float* smooth = (const float*)d_in[1];
    const float* w      = (const float*)d_in[2];
    const float* la     = (const float*)d_in[3];
    const float* lb     = (const float*)d_in[4];
    const float* bias   = (const float*)d_in[5];
    float* out = (float*)d_out;

    void *p_xcat = nullptr, *p_wcat = nullptr, *p_xs = nullptr;
    cudaGetSymbolAddress(&p_xcat, g_xcat);
    cudaGetSymbolAddress(&p_wcat, g_wcat);
    cudaGetSymbolAddress(&p_xs,   g_xs);

    build_wcat_kernel<<<(OUT_F * KTOT) / 256, 256>>>(w, lb, (__half*)p_wcat);
    quant_x_kernel<<<(MROWS * IN_F / 16) / 128, 128>>>(x, smooth, (__half*)p_xs, (__half*)p_xcat);
    zero_tail_kernel<<<64, 256>>>((__half*)p_xcat);
    lora_t_kernel<<<MROWS / 16, 256>>>((const __half*)p_xs, la, (__half*)p_xcat);

    void* fnp = nullptr;
    cudaDriverEntryPointQueryResult qr;
    cudaGetDriverEntryPointByVersion("cuTensorMapEncodeTiled", &fnp, 12000,
                                     cudaEnableDefault, &qr);
    tmap_fn_t enc = (tmap_fn_t)fnp;

    CUtensorMap ta, tb;
    cuuint64_t dims[2]    = {(cuuint64_t)KTOT, (cuuint64_t)MROWS};
    cuuint64_t strides[1] = {(cuuint64_t)KTOT * 2};
    cuuint32_t es[2]      = {1, 1};
    cuuint32_t boxA[2]    = {TK, TM};
    cuuint32_t boxB[2]    = {TK, TN};
    enc(&ta, CU_TENSOR_MAP_DATA_TYPE_FLOAT16, 2, p_xcat, dims, strides, boxA, es,
        CU_TENSOR_MAP_INTERLEAVE_NONE, CU_TENSOR_MAP_SWIZZLE_128B,
        CU_TENSOR_MAP_L2_PROMOTION_L2_128B, CU_TENSOR_MAP_FLOAT_OOB_FILL_NONE);
    enc(&tb, CU_TENSOR_MAP_DATA_TYPE_FLOAT16, 2, p_wcat, dims, strides, boxB, es,
        CU_TENSOR_MAP_INTERLEAVE_NONE, CU_TENSOR_MAP_SWIZZLE_128B,
        CU_TENSOR_MAP_L2_PROMOTION_L2_128B, CU_TENSOR_MAP_FLOAT_OOB_FILL_NONE);

    cudaFuncSetAttribute(gemm_kernel, cudaFuncAttributeMaxDynamicSharedMemorySize, SMEM_TOTAL);
    dim3 grid(MROWS / TM, OUT_F / TN);
    gemm_kernel<<<grid, 160, SMEM_TOTAL>>>(ta, tb, bias, out);
}

// round 6
// speedup vs baseline: 1.1509x; 1.1509x over previous
#include <cuda_runtime.h>
#include <cuda_fp16.h>
#include <cuda.h>
#include <cstdint>
#include <cstddef>

#define IN_F   4096
#define OUT_F  4096
#define MROWS  4096
#define RANK   32
#define KTOT   4160
#define TM     128
#define TN     128
#define TK     64
#define NKT    65
#define PSTG   3
#define KSPLIT 4
#define STAGE_A_BYTES (TM*TK*2)          // 16 KB
#define STAGE_B_BYTES (TN*TK*2)          // 16 KB
#define STAGE_BYTES   (STAGE_A_BYTES + STAGE_B_BYTES)
#define SMEM_HDR      1024
#define SMEM_TOTAL    (SMEM_HDR + PSTG*STAGE_BYTES)   // 99328 -> 2 CTAs/SM

__device__ __half g_xcat[(size_t)MROWS * KTOT];
__device__ __half g_wcat[(size_t)OUT_F * KTOT];
__device__ __half g_xs  [(size_t)MROWS * IN_F];
__device__ float  g_tp  [(size_t)KSPLIT * MROWS * RANK];   // lora split-K partials

__device__ __forceinline__ uint32_t smem_u32(const void* p) {
    uint32_t a;
    asm("{ .reg .u64 t; cvta.to.shared.u64 t, %1; cvt.u32.u64 %0, t; }" : "=r"(a) : "l"(p));
    return a;
}

#define MBAR_INIT(addr, cnt) \
    asm volatile("mbarrier.init.shared.b64 [%0], %1;" :: "r"(addr), "r"((uint32_t)(cnt)) : "memory")
#define MBAR_EXPECT_TX(addr, b) \
    asm volatile("mbarrier.arrive.expect_tx.shared.b64 _, [%0], %1;" :: "r"(addr), "r"((uint32_t)(b)) : "memory")
#define MBAR_ARRIVE(addr) \
    asm volatile("mbarrier.arrive.shared.b64 _, [%0];" :: "r"(addr) : "memory")
#define MBAR_WAIT(addr, ph) do {                                              \
    uint32_t _m = (addr), _p = (uint32_t)(ph), _d;                            \
    asm volatile("{\n\t.reg .pred p;\n\t"                                     \
        "mbarrier.try_wait.parity.acquire.cta.shared::cta.b64 p, [%1], %2;\n\t" \
        "selp.b32 %0, 1, 0, p;\n\t}"                                          \
        : "=r"(_d) : "r"(_m), "r"(_p) : "memory");                            \
    if (!_d) {                                                                \
        asm volatile("{\n\t.reg .pred P1;\n\t"                                \
            "WL%=:\n\t"                                                       \
            "mbarrier.try_wait.parity.acquire.cta.shared::cta.b64 P1, [%0], %1, 0x989680;\n\t" \
            "@P1 bra.uni WD%=;\n\t"                                           \
            "bra.uni WL%=;\n\t"                                               \
            "WD%=:\n\t}" :: "r"(_m), "r"(_p) : "memory");                     \
    }                                                                         \
} while (0)

__device__ __forceinline__ void tma_load_2d(uint32_t smem_addr, const CUtensorMap* map,
                                            int cx, int cy, uint32_t mbar) {
    asm volatile(
        "cp.async.bulk.tensor.2d.shared::cta.global.tile.mbarrier::complete_tx::bytes "
        "[%0], [%1, {%2, %3}], [%4];"
        :: "r"(smem_addr), "l"((unsigned long long)(uintptr_t)map),
           "r"(cx), "r"(cy), "r"(mbar) : "memory");
}

__device__ __forceinline__ void ldsm_x4(uint32_t& r0, uint32_t& r1, uint32_t& r2, uint32_t& r3,
                                        uint32_t addr) {
    asm volatile("ldmatrix.sync.aligned.m8n8.x4.shared.b16 {%0,%1,%2,%3}, [%4];"
                 : "=r"(r0), "=r"(r1), "=r"(r2), "=r"(r3) : "r"(addr));
}

__device__ __forceinline__ void mma16816(float* c, const uint32_t* a, uint32_t b0, uint32_t b1) {
    asm volatile(
        "mma.sync.aligned.m16n8k16.row.col.f32.f16.f16.f32 "
        "{%0,%1,%2,%3}, {%4,%5,%6,%7}, {%8,%9}, {%0,%1,%2,%3};"
        : "+f"(c[0]), "+f"(c[1]), "+f"(c[2]), "+f"(c[3])
        : "r"(a[0]), "r"(a[1]), "r"(a[2]), "r"(a[3]), "r"(b0), "r"(b1));
}

// ---- prologue 1: w_cat = [W | lora_b | 0] fp16 ----
__global__ void build_wcat_kernel(const float* __restrict__ w,
                                  const float* __restrict__ lb,
                                  __half* __restrict__ wcat) {
    int idx = blockIdx.x * 256 + threadIdx.x;
    int o = idx / KTOT;
    int c = idx - o * KTOT;
    float v;
    if (c < IN_F)             v = w[(size_t)o * IN_F + c];
    else if (c < IN_F + RANK) v = lb[(size_t)o * RANK + (c - IN_F)];
    else                      v = 0.0f;
    wcat[idx] = __float2half(v);
}

// ---- prologue 2: smooth + exact NVFP4 fake-quant ----
__global__ void quant_x_kernel(const float* __restrict__ x,
                               const float* __restrict__ ss,
                               __half* __restrict__ xs,
                               __half* __restrict__ xcat) {
    int b = blockIdx.x * blockDim.x + threadIdx.x;   // 16-elem block index
    int row = b >> 8;
    int kb  = (b & 255) << 4;
    const float4* xp = reinterpret_cast<const float4*>(x + (size_t)row * IN_F + kb);
    const float4* sp = reinterpret_cast<const float4*>(ss + kb);
    float v[16];
#pragma unroll
    for (int i = 0; i < 4; i++) {
        float4 a = xp[i]; float4 s = sp[i];
        v[4*i+0] = a.x * s.x; v[4*i+1] = a.y * s.y;
        v[4*i+2] = a.z * s.z; v[4*i+3] = a.w * s.w;
    }
    float amax = 0.0f;
#pragma unroll
    for (int i = 0; i < 16; i++) amax = fmaxf(amax, fabsf(v[i]));
    amax = fmaxf(amax, 1e-12f);
    float scale = amax / 6.0f;
    __align__(16) __half h_s[16];
    __align__(16) __half h_q[16];
#pragma unroll
    for (int i = 0; i < 16; i++) {
        h_s[i] = __float2half(v[i]);
        float an = fabsf(v[i]) / scale;
        float lvl;
        if      (an <= 0.25f) lvl = 0.0f;   // <= : tie -> lower level (argmin-first)
        else if (an <= 0.75f) lvl = 0.5f;
        else if (an <= 1.25f) lvl = 1.0f;
        else if (an <= 1.75f) lvl = 1.5f;
        else if (an <= 2.5f)  lvl = 2.0f;
        else if (an <= 3.5f)  lvl = 3.0f;
        else if (an <= 5.0f)  lvl = 4.0f;
        else                  lvl = 6.0f;
        h_q[i] = __float2half(copysignf(lvl * scale, v[i]));
    }
    uint4* d1 = reinterpret_cast<uint4*>(xs + (size_t)row * IN_F + kb);
    d1[0] = reinterpret_cast<uint4*>(h_s)[0];
    d1[1] = reinterpret_cast<uint4*>(h_s)[1];
    uint4* d2 = reinterpret_cast<uint4*>(xcat + (size_t)row * KTOT + kb);
    d2[0] = reinterpret_cast<uint4*>(h_q)[0];
    d2[1] = reinterpret_cast<uint4*>(h_q)[1];
}

__global__ void zero_tail_kernel(__half* __restrict__ xcat) {
    int idx = blockIdx.x * blockDim.x + threadIdx.x;  // 4096*4 uint4
    int row = idx >> 2;
    int j   = idx & 3;
    reinterpret_cast<uint4*>(xcat + (size_t)row * KTOT + IN_F + RANK)[j] = make_uint4(0,0,0,0);
}

// ---- prologue 3a: split-K partials of t = x_s @ lora_a^T ----
__global__ void lora_t_part(const __half* __restrict__ xs,
                            const float* __restrict__ la,
                            float* __restrict__ tp) {
    __shared__ float  sa[RANK][130];     // 130 pad: conflict-free float2 column reads
    __shared__ __half sx[16][128];
    int row0 = blockIdx.x * 16;
    int kz   = blockIdx.y;               // 0..KSPLIT-1
    int tid  = threadIdx.x;
    int lane = tid & 31;                 // rank index
    int warp = tid >> 5;                 // 2 rows per warp
    float acc0 = 0.0f, acc1 = 0.0f;
    int kbeg = kz * (IN_F / KSPLIT);
    int kend = kbeg + (IN_F / KSPLIT);
    for (int k0 = kbeg; k0 < kend; k0 += 128) {
        __syncthreads();
        for (int idx = tid; idx < RANK * 128; idx += 256) {
            int r = idx >> 7, kk = idx & 127;
            sa[r][kk] = la[(size_t)r * IN_F + k0 + kk];
        }
        for (int idx = tid; idx < 16 * 64; idx += 256) {
            int r = idx >> 6, kk2 = idx & 63;
            reinterpret_cast<uint32_t*>(&sx[r][0])[kk2] =
                reinterpret_cast<const uint32_t*>(xs + (size_t)(row0 + r) * IN_F + k0)[kk2];
        }
        __syncthreads();
        int r0 = warp * 2;
        const __half2* px0 = reinterpret_cast<const __half2*>(&sx[r0][0]);
        const __half2* px1 = reinterpret_cast<const __half2*>(&sx[r0 + 1][0]);
        const float2*  pa  = reinterpret_cast<const float2*>(&sa[lane][0]);
#pragma unroll 16
        for (int kk = 0; kk < 64; kk++) {
            float2 av = pa[kk];
            float2 x0 = __half22float2(px0[kk]);
            float2 x1 = __half22float2(px1[kk]);
            acc0 = fmaf(x0.x, av.x, acc0); acc0 = fmaf(x0.y, av.y, acc0);
            acc1 = fmaf(x1.x, av.x, acc1); acc1 = fmaf(x1.y, av.y, acc1);
        }
    }
    size_t base = (size_t)kz * MROWS * RANK;
    tp[base + (size_t)(row0 + warp * 2)     * RANK + lane] = acc0;
    tp[base + (size_t)(row0 + warp * 2 + 1) * RANK + lane] = acc1;
}

// ---- prologue 3b: reduce partials -> x_cat cols [4096,4128) ----
__global__ void lora_t_reduce(const float* __restrict__ tp,
                              __half* __restrict__ xcat) {
    int idx = blockIdx.x * 256 + threadIdx.x;    // < 4096*32
    int row = idx >> 5;
    int r   = idx & 31;
    float s = tp[idx];
#pragma unroll
    for (int z = 1; z < KSPLIT; z++) s += tp[(size_t)z * MROWS * RANK + idx];
    xcat[(size_t)row * KTOT + IN_F + r] = __float2half(s);
}

// ---- main GEMM: 128x128 CTA tile, warp tile 64x64, mma.sync m16n8k16 ----
#define OFF_FULL(s)  (16u + 8u * (s))
#define OFF_EMPTY(s) (64u + 8u * (s))
#define OFF_A(s)     (SMEM_HDR + (s) * STAGE_BYTES)
#define OFF_B(s)     (OFF_A(s) + STAGE_A_BYTES)

__global__ void __launch_bounds__(160, 2)
gemm_kernel(const __grid_constant__ CUtensorMap tma_a,
            const __grid_constant__ CUtensorMap tma_b,
            const float* __restrict__ bias,
            float* __restrict__ out) {
    extern __shared__ __align__(1024) char smem_buf[];
    uint32_t sbase = smem_u32(smem_buf);
    int tid  = threadIdx.x;
    int warp = tid >> 5;
    int lane = tid & 31;
    int m0 = blockIdx.x * TM;
    int n0 = blockIdx.y * TN;

    if (tid == 0) {
        for (int s = 0; s < PSTG; s++) {
            MBAR_INIT(sbase + OFF_FULL(s), 1);
            MBAR_INIT(sbase + OFF_EMPTY(s), 4);    // one elected arrive per consumer warp
        }
    }
    __syncthreads();

    if (warp == 4) {
        // ------------- TMA producer (lane 0) -------------
        if (lane == 0) {
            int s = 0;
            for (int kt = 0; kt < NKT; kt++) {
                if (kt >= PSTG) MBAR_WAIT(sbase + OFF_EMPTY(s), ((kt - PSTG) / PSTG) & 1);
                MBAR_EXPECT_TX(sbase + OFF_FULL(s), STAGE_BYTES);
                tma_load_2d(sbase + OFF_A(s), &tma_a, kt * TK, m0, sbase + OFF_FULL(s));
                tma_load_2d(sbase + OFF_B(s), &tma_b, kt * TK, n0, sbase + OFF_FULL(s));
                if (++s == PSTG) s = 0;
            }
        }
        return;
    }

    // ------------- consumers: 4 warps, 2x2 grid, 64x64 each -------------
    int wm = (warp >> 1) * 64;
    int wn = (warp & 1) * 64;
    int lrow = (lane & 7) + ((lane >> 3) & 1) * 8;
    int lhi  = (lane >> 4) & 1;

    uint32_t arow[4], asw[4], brow[4], bsw[4];
#pragma unroll
    for (int i = 0; i < 4; i++) {
        int ra = wm + i * 16 + lrow;
        arow[i] = (uint32_t)ra * 128u; asw[i] = (uint32_t)(ra & 7);
        int rb = wn + i * 16 + lrow;
        brow[i] = (uint32_t)rb * 128u; bsw[i] = (uint32_t)(rb & 7);
    }

    float acc[4][8][4];
#pragma unroll
    for (int i = 0; i < 4; i++)
#pragma unroll
        for (int j = 0; j < 8; j++)
#pragma unroll
            for (int q = 0; q < 4; q++) acc[i][j][q] = 0.0f;

    int s = 0;
    for (int kt = 0; kt < NKT; kt++) {
        int ph = (kt / PSTG) & 1;
        MBAR_WAIT(sbase + OFF_FULL(s), ph);
        uint32_t aS = sbase + OFF_A(s);
        uint32_t bS = sbase + OFF_B(s);
#pragma unroll
        for (int ks = 0; ks < 4; ks++) {
            uint32_t chunk = (uint32_t)(ks * 2 + lhi);
            uint32_t a[4][4];
            uint32_t bf[8][2];
#pragma unroll
            for (int mi = 0; mi < 4; mi++)
                ldsm_x4(a[mi][0], a[mi][1], a[mi][2], a[mi][3],
                        aS + arow[mi] + (((chunk ^ asw[mi]) & 7u) << 4));
#pragma unroll
            for (int nj = 0; nj < 4; nj++) {
                uint32_t r0, r1, r2, r3;
                ldsm_x4(r0, r1, r2, r3,
                        bS + brow[nj] + (((chunk ^ bsw[nj]) & 7u) << 4));
                bf[2*nj][0] = r0; bf[2*nj][1] = r2;
                bf[2*nj+1][0] = r1; bf[2*nj+1][1] = r3;
            }
#pragma unroll
            for (int mi = 0; mi < 4; mi++)
#pragma unroll
                for (int ni = 0; ni < 8; ni++)
                    mma16816(acc[mi][ni], a[mi], bf[ni][0], bf[ni][1]);
        }
        if (lane == 0) MBAR_ARRIVE(sbase + OFF_EMPTY(s));
        if (++s == PSTG) s = 0;
    }

    // ------------- epilogue: bias + store -------------
    int crow = lane >> 2;
    int ccol = (lane & 3) * 2;
    float2 bfrag[8];
#pragma unroll
    for (int ni = 0; ni < 8; ni++)
        bfrag[ni] = __ldg(reinterpret_cast<const float2*>(bias + n0 + wn + ni * 8 + ccol));
#pragma unroll
    for (int mi = 0; mi < 4; mi++) {
        int m_lo = m0 + wm + mi * 16 + crow;
#pragma unroll
        for (int ni = 0; ni < 8; ni++) {
            int col = n0 + wn + ni * 8 + ccol;
            float2 v0, v1;
            v0.x = acc[mi][ni][0] + bfrag[ni].x;
            v0.y = acc[mi][ni][1] + bfrag[ni].y;
            v1.x = acc[mi][ni][2] + bfrag[ni].x;
            v1.y = acc[mi][ni][3] + bfrag[ni].y;
            *reinterpret_cast<float2*>(out + (size_t)m_lo * OUT_F + col) = v0;
            *reinterpret_cast<float2*>(out + (size_t)(m_lo + 8) * OUT_F + col) = v1;
        }
    }
}

typedef CUresult (*tmap_fn_t)(CUtensorMap*, CUtensorMapDataType, cuuint32_t, void*,
                              const cuuint64_t*, const cuuint64_t*, const cuuint32_t*,
                              const cuuint32_t*, CUtensorMapInterleave, CUtensorMapSwizzle,
                              CUtensorMapL2promotion, CUtensorMapFloatOOBfill);

extern "C" void kernel_launch(void* const* d_in, const int* in_sizes, int n_in,
                              void* d_out, int out_size) {
    (void)in_sizes; (void)n_in; (void)out_size;
    const float* x      = (const float*)d_in[0];
    const float* smooth = (const float*)d_in[1];
    const float* w      = (const float*)d_in[2];
    const float* la     = (const float*)d_in[3];
    const float* lb     = (const float*)d_in[4];
    const float* bias   = (const float*)d_in[5];
    float* out = (float*)d_out;

    void *p_xcat = nullptr, *p_wcat = nullptr, *p_xs = nullptr, *p_tp = nullptr;
    cudaGetSymbolAddress(&p_xcat, g_xcat);
    cudaGetSymbolAddress(&p_wcat, g_wcat);
    cudaGetSymbolAddress(&p_xs,   g_xs);
    cudaGetSymbolAddress(&p_tp,   g_tp);

    build_wcat_kernel<<<(OUT_F * KTOT) / 256, 256>>>(w, lb, (__half*)p_wcat);
    quant_x_kernel<<<(MROWS * IN_F / 16) / 128, 128>>>(x, smooth, (__half*)p_xs, (__half*)p_xcat);
    zero_tail_kernel<<<64, 256>>>((__half*)p_xcat);
    {
        dim3 lg(MROWS / 16, KSPLIT);
        lora_t_part<<<lg, 256>>>((const __half*)p_xs, la, (float*)p_tp);
        lora_t_reduce<<<(MROWS * RANK) / 256, 256>>>((const float*)p_tp, (__half*)p_xcat);
    }

    void* fnp = nullptr;
    cudaDriverEntryPointQueryResult qr;
    cudaGetDriverEntryPointByVersion("cuTensorMapEncodeTiled", &fnp, 12000,
                                     cudaEnableDefault, &qr);
    tmap_fn_t enc = (tmap_fn_t)fnp;

    CUtensorMap ta, tb;
    cuuint64_t dims[2]    = {(cuuint64_t)KTOT, (cuuint64_t)MROWS};
    cuuint64_t strides[1] = {(cuuint64_t)KTOT * 2};
    cuuint32_t es[2]      = {1, 1};
    cuuint32_t boxA[2]    = {TK, TM};
    cuuint32_t boxB[2]    = {TK, TN};
    enc(&ta, CU_TENSOR_MAP_DATA_TYPE_FLOAT16, 2, p_xcat, dims, strides, boxA, es,
        CU_TENSOR_MAP_INTERLEAVE_NONE, CU_TENSOR_MAP_SWIZZLE_128B,
        CU_TENSOR_MAP_L2_PROMOTION_L2_128B, CU_TENSOR_MAP_FLOAT_OOB_FILL_NONE);
    enc(&tb, CU_TENSOR_MAP_DATA_TYPE_FLOAT16, 2, p_wcat, dims, strides, boxB, es,
        CU_TENSOR_MAP_INTERLEAVE_NONE, CU_TENSOR_MAP_SWIZZLE_128B,
        CU_TENSOR_MAP_L2_PROMOTION_L2_128B, CU_TENSOR_MAP_FLOAT_OOB_FILL_NONE);

    cudaFuncSetAttribute(gemm_kernel, cudaFuncAttributeMaxDynamicSharedMemorySize, SMEM_TOTAL);
    dim3 grid(MROWS / TM, OUT_F / TN);
    gemm_kernel<<<grid, 160, SMEM_TOTAL>>>(ta, tb, bias, out);
}

// round 8
// speedup vs baseline: 1.2050x; 1.0470x over previous
#include <cuda_runtime.h>
#include <cuda_fp16.h>
#include <cuda.h>
#include <cstdint>
#include <cstddef>

#define IN_F   4096
#define OUT_F  4096
#define MROWS  4096
#define RANK   32
#define KTOT   4160
#define TM     256
#define TN     128
#define TK     64
#define NKT    65
#define PSTG   4
#define STAGE_A_BYTES (TM*TK*2)          // 32 KB
#define STAGE_B_BYTES (TN*TK*2)          // 16 KB
#define STAGE_BYTES   (STAGE_A_BYTES + STAGE_B_BYTES)
#define SMEM_HDR      1024
#define SMEM_TOTAL    (SMEM_HDR + PSTG*STAGE_BYTES)   // 197632

#define KSPLIT 8

__device__ __half g_xcat[(size_t)MROWS * KTOT];
__device__ __half g_wcat[(size_t)OUT_F * KTOT];
__device__ __half g_xs  [(size_t)MROWS * IN_F];
__device__ __half g_lah [(size_t)RANK * IN_F];
__device__ float  g_tp  [(size_t)KSPLIT * MROWS * RANK];

__device__ __forceinline__ uint32_t smem_u32(const void* p) {
    uint32_t a;
    asm("{ .reg .u64 t; cvta.to.shared.u64 t, %1; cvt.u32.u64 %0, t; }" : "=r"(a) : "l"(p));
    return a;
}

#define MBAR_INIT(addr, cnt) \
    asm volatile("mbarrier.init.shared.b64 [%0], %1;" :: "r"(addr), "r"((uint32_t)(cnt)) : "memory")
#define MBAR_EXPECT_TX(addr, b) \
    asm volatile("mbarrier.arrive.expect_tx.shared.b64 _, [%0], %1;" :: "r"(addr), "r"((uint32_t)(b)) : "memory")
#define MBAR_ARRIVE(addr) \
    asm volatile("mbarrier.arrive.shared.b64 _, [%0];" :: "r"(addr) : "memory")
#define MBAR_WAIT(addr, ph) do {                                              \
    uint32_t _m = (addr), _p = (uint32_t)(ph), _d;                            \
    asm volatile("{\n\t.reg .pred p;\n\t"                                     \
        "mbarrier.try_wait.parity.acquire.cta.shared::cta.b64 p, [%1], %2;\n\t" \
        "selp.b32 %0, 1, 0, p;\n\t}"                                          \
        : "=r"(_d) : "r"(_m), "r"(_p) : "memory");                            \
    if (!_d) {                                                                \
        asm volatile("{\n\t.reg .pred P1;\n\t"                                \
            "WL%=:\n\t"                                                       \
            "mbarrier.try_wait.parity.acquire.cta.shared::cta.b64 P1, [%0], %1, 0x989680;\n\t" \
            "@P1 bra.uni WD%=;\n\t"                                           \
            "bra.uni WL%=;\n\t"                                               \
            "WD%=:\n\t}" :: "r"(_m), "r"(_p) : "memory");                     \
    }                                                                         \
} while (0)

__device__ __forceinline__ void tma_load_2d(uint32_t smem_addr, const CUtensorMap* map,
                                            int cx, int cy, uint32_t mbar) {
    asm volatile(
        "cp.async.bulk.tensor.2d.shared::cta.global.tile.mbarrier::complete_tx::bytes "
        "[%0], [%1, {%2, %3}], [%4];"
        :: "r"(smem_addr), "l"((unsigned long long)(uintptr_t)map),
           "r"(cx), "r"(cy), "r"(mbar) : "memory");
}

__device__ __forceinline__ void ldsm_x4(uint32_t& r0, uint32_t& r1, uint32_t& r2, uint32_t& r3,
                                        uint32_t addr) {
    asm volatile("ldmatrix.sync.aligned.m8n8.x4.shared.b16 {%0,%1,%2,%3}, [%4];"
                 : "=r"(r0), "=r"(r1), "=r"(r2), "=r"(r3) : "r"(addr));
}

__device__ __forceinline__ void mma16816(float* c, const uint32_t* a, uint32_t b0, uint32_t b1) {
    asm volatile(
        "mma.sync.aligned.m16n8k16.row.col.f32.f16.f16.f32 "
        "{%0,%1,%2,%3}, {%4,%5,%6,%7}, {%8,%9}, {%0,%1,%2,%3};"
        : "+f"(c[0]), "+f"(c[1]), "+f"(c[2]), "+f"(c[3])
        : "r"(a[0]), "r"(a[1]), "r"(a[2]), "r"(a[3]), "r"(b0), "r"(b1));
}

// ---- prologue 1: w_cat = [W | lora_b | 0] fp16 ----
__global__ void build_wcat_kernel(const float* __restrict__ w,
                                  const float* __restrict__ lb,
                                  __half* __restrict__ wcat) {
    int idx = blockIdx.x * 256 + threadIdx.x;
    int o = idx / KTOT;
    int c = idx - o * KTOT;
    float v;
    if (c < IN_F)             v = w[(size_t)o * IN_F + c];
    else if (c < IN_F + RANK) v = lb[(size_t)o * RANK + (c - IN_F)];
    else                      v = 0.0f;
    wcat[idx] = __float2half(v);
}

// ---- prologue 1b: lora_a -> fp16 ----
__global__ void build_lah_kernel(const float* __restrict__ la,
                                 __half* __restrict__ lah) {
    int idx = blockIdx.x * 256 + threadIdx.x;   // < 32*4096
    lah[idx] = __float2half(la[idx]);
}

// ---- prologue 2: smooth + exact NVFP4 fake-quant ----
__global__ void quant_x_kernel(const float* __restrict__ x,
                               const float* __restrict__ ss,
                               __half* __restrict__ xs,
                               __half* __restrict__ xcat) {
    int b = blockIdx.x * blockDim.x + threadIdx.x;
    int row = b >> 8;
    int kb  = (b & 255) << 4;
    const float4* xp = reinterpret_cast<const float4*>(x + (size_t)row * IN_F + kb);
    const float4* sp = reinterpret_cast<const float4*>(ss + kb);
    float v[16];
#pragma unroll
    for (int i = 0; i < 4; i++) {
        float4 a = xp[i]; float4 s = sp[i];
        v[4*i+0] = a.x * s.x; v[4*i+1] = a.y * s.y;
        v[4*i+2] = a.z * s.z; v[4*i+3] = a.w * s.w;
    }
    float amax = 0.0f;
#pragma unroll
    for (int i = 0; i < 16; i++) amax = fmaxf(amax, fabsf(v[i]));
    amax = fmaxf(amax, 1e-12f);
    float scale = amax / 6.0f;
    __align__(16) __half h_s[16];
    __align__(16) __half h_q[16];
#pragma unroll
    for (int i = 0; i < 16; i++) {
        h_s[i] = __float2half(v[i]);
        float an = fabsf(v[i]) / scale;
        float lvl;
        if      (an <= 0.25f) lvl = 0.0f;
        else if (an <= 0.75f) lvl = 0.5f;
        else if (an <= 1.25f) lvl = 1.0f;
        else if (an <= 1.75f) lvl = 1.5f;
        else if (an <= 2.5f)  lvl = 2.0f;
        else if (an <= 3.5f)  lvl = 3.0f;
        else if (an <= 5.0f)  lvl = 4.0f;
        else                  lvl = 6.0f;
        h_q[i] = __float2half(copysignf(lvl * scale, v[i]));
    }
    uint4* d1 = reinterpret_cast<uint4*>(xs + (size_t)row * IN_F + kb);
    d1[0] = reinterpret_cast<uint4*>(h_s)[0];
    d1[1] = reinterpret_cast<uint4*>(h_s)[1];
    uint4* d2 = reinterpret_cast<uint4*>(xcat + (size_t)row * KTOT + kb);
    d2[0] = reinterpret_cast<uint4*>(h_q)[0];
    d2[1] = reinterpret_cast<uint4*>(h_q)[1];
}

__global__ void zero_tail_kernel(__half* __restrict__ xcat) {
    int idx = blockIdx.x * blockDim.x + threadIdx.x;
    int row = idx >> 2;
    int j   = idx & 3;
    reinterpret_cast<uint4*>(xcat + (size_t)row * KTOT + IN_F + RANK)[j] = make_uint4(0,0,0,0);
}

// ---- prologue 3a: t partials via mma: [128 x 32] per block, K chunk 512 ----
#define LPSTG 2
#define L_A_BYTES (128*64*2)
#define L_B_BYTES (32*64*2)
#define L_STAGE   (L_A_BYTES + L_B_BYTES)
#define L_SMEM    (1024 + LPSTG*L_STAGE)
#define LOFF_FULL(s)  (16u + 8u * (s))
#define LOFF_EMPTY(s) (48u + 8u * (s))
#define LOFF_A(s)     (1024u + (s) * L_STAGE)
#define LOFF_B(s)     (LOFF_A(s) + L_A_BYTES)

__global__ void __launch_bounds__(160, 1)
lora_mma_kernel(const __grid_constant__ CUtensorMap tma_xs,
                const __grid_constant__ CUtensorMap tma_la,
                float* __restrict__ tp) {
    extern __shared__ __align__(1024) char smem_buf[];
    uint32_t sbase = smem_u32(smem_buf);
    int tid  = threadIdx.x;
    int warp = tid >> 5;
    int lane = tid & 31;
    int m0 = blockIdx.x * 128;
    int kz = blockIdx.y;
    int kt0 = kz * 8;                       // 8 k-tiles of 64 per split

    if (tid == 0) {
        for (int s = 0; s < LPSTG; s++) {
            MBAR_INIT(sbase + LOFF_FULL(s), 1);
            MBAR_INIT(sbase + LOFF_EMPTY(s), 4);
        }
    }
    __syncthreads();

    if (warp == 4) {
        if (lane == 0) {
            int s = 0;
            for (int kt = 0; kt < 8; kt++) {
                if (kt >= LPSTG) MBAR_WAIT(sbase + LOFF_EMPTY(s), ((kt - LPSTG) / LPSTG) & 1);
                MBAR_EXPECT_TX(sbase + LOFF_FULL(s), L_STAGE);
                tma_load_2d(sbase + LOFF_A(s), &tma_xs, (kt0 + kt) * 64, m0, sbase + LOFF_FULL(s));
                tma_load_2d(sbase + LOFF_B(s), &tma_la, (kt0 + kt) * 64, 0,  sbase + LOFF_FULL(s));
                if (++s == LPSTG) s = 0;
            }
        }
        return;
    }

    int wm = warp * 32;
    int lrow = (lane & 7) + ((lane >> 3) & 1) * 8;
    int lhi  = (lane >> 4) & 1;
    uint32_t arow[2], asw[2], brow[2], bsw[2];
#pragma unroll
    for (int i = 0; i < 2; i++) {
        int ra = wm + i * 16 + lrow;
        arow[i] = (uint32_t)ra * 128u; asw[i] = (uint32_t)(ra & 7);
        int rb = i * 16 + lrow;
        brow[i] = (uint32_t)rb * 128u; bsw[i] = (uint32_t)(rb & 7);
    }
    float acc[2][4][4];
#pragma unroll
    for (int i = 0; i < 2; i++)
#pragma unroll
        for (int j = 0; j < 4; j++)
#pragma unroll
            for (int q = 0; q < 4; q++) acc[i][j][q] = 0.0f;

    int s = 0;
    for (int kt = 0; kt < 8; kt++) {
        MBAR_WAIT(sbase + LOFF_FULL(s), (kt / LPSTG) & 1);
        uint32_t aS = sbase + LOFF_A(s);
        uint32_t bS = sbase + LOFF_B(s);
#pragma unroll
        for (int ks = 0; ks < 4; ks++) {
            uint32_t chunk = (uint32_t)(ks * 2 + lhi);
            uint32_t a[2][4];
            uint32_t bf[4][2];
#pragma unroll
            for (int mi = 0; mi < 2; mi++)
                ldsm_x4(a[mi][0], a[mi][1], a[mi][2], a[mi][3],
                        aS + arow[mi] + (((chunk ^ asw[mi]) & 7u) << 4));
#pragma unroll
            for (int nj = 0; nj < 2; nj++) {
                uint32_t r0, r1, r2, r3;
                ldsm_x4(r0, r1, r2, r3,
                        bS + brow[nj] + (((chunk ^ bsw[nj]) & 7u) << 4));
                bf[2*nj][0] = r0; bf[2*nj][1] = r2;
                bf[2*nj+1][0] = r1; bf[2*nj+1][1] = r3;
            }
#pragma unroll
            for (int mi = 0; mi < 2; mi++)
#pragma unroll
                for (int ni = 0; ni < 4; ni++)
                    mma16816(acc[mi][ni], a[mi], bf[ni][0], bf[ni][1]);
        }
        if (lane == 0) MBAR_ARRIVE(sbase + LOFF_EMPTY(s));
        if (++s == LPSTG) s = 0;
    }

    float* tpb = tp + (size_t)kz * MROWS * RANK;
    int crow = lane >> 2;
    int ccol = (lane & 3) * 2;
#pragma unroll
    for (int mi = 0; mi < 2; mi++) {
        int m = m0 + wm + mi * 16 + crow;
#pragma unroll
        for (int ni = 0; ni < 4; ni++) {
            int c = ni * 8 + ccol;
            float2 v0 = make_float2(acc[mi][ni][0], acc[mi][ni][1]);
            float2 v1 = make_float2(acc[mi][ni][2], acc[mi][ni][3]);
            *reinterpret_cast<float2*>(tpb + (size_t)m * RANK + c) = v0;
            *reinterpret_cast<float2*>(tpb + (size_t)(m + 8) * RANK + c) = v1;
        }
    }
}

// ---- prologue 3b: reduce partials -> x_cat cols [4096,4128) ----
__global__ void lora_t_reduce(const float* __restrict__ tp,
                              __half* __restrict__ xcat) {
    int idx = blockIdx.x * 256 + threadIdx.x;
    int row = idx >> 5;
    int r   = idx & 31;
    float s = tp[idx];
#pragma unroll
    for (int z = 1; z < KSPLIT; z++) s += tp[(size_t)z * MROWS * RANK + idx];
    xcat[(size_t)row * KTOT + IN_F + r] = __float2half(s);
}

// ---- main GEMM: 256x128 CTA tile, 8 consumer warps (64x64), mma.sync ----
#define OFF_FULL(s)  (16u + 8u * (s))
#define OFF_EMPTY(s) (64u + 8u * (s))
#define OFF_A(s)     (SMEM_HDR + (s) * STAGE_BYTES)
#define OFF_B(s)     (OFF_A(s) + STAGE_A_BYTES)

__global__ void __launch_bounds__(288, 1)
gemm_kernel(const __grid_constant__ CUtensorMap tma_a,
            const __grid_constant__ CUtensorMap tma_b,
            const float* __restrict__ bias,
            float* __restrict__ out) {
    extern __shared__ __align__(1024) char smem_buf[];
    uint32_t sbase = smem_u32(smem_buf);
    int tid  = threadIdx.x;
    int warp = tid >> 5;
    int lane = tid & 31;
    int m0 = blockIdx.x * TM;
    int n0 = blockIdx.y * TN;

    if (tid == 0) {
        for (int s = 0; s < PSTG; s++) {
            MBAR_INIT(sbase + OFF_FULL(s), 1);
            MBAR_INIT(sbase + OFF_EMPTY(s), 8);
        }
    }
    __syncthreads();

    if (warp == 8) {
        if (lane == 0) {
            int s = 0;
            for (int kt = 0; kt < NKT; kt++) {
                if (kt >= PSTG) MBAR_WAIT(sbase + OFF_EMPTY(s), ((kt - PSTG) / PSTG) & 1);
                MBAR_EXPECT_TX(sbase + OFF_FULL(s), STAGE_BYTES);
                tma_load_2d(sbase + OFF_A(s), &tma_a, kt * TK, m0, sbase + OFF_FULL(s));
                tma_load_2d(sbase + OFF_B(s), &tma_b, kt * TK, n0, sbase + OFF_FULL(s));
                if (++s == PSTG) s = 0;
            }
        }
        return;
    }

    // 8 consumers: 4 (m) x 2 (n) grid of 64x64 warp tiles
    int wm = (warp >> 1) * 64;
    int wn = (warp & 1) * 64;
    int lrow = (lane & 7) + ((lane >> 3) & 1) * 8;
    int lhi  = (lane >> 4) & 1;

    uint32_t arow[4], asw[4], brow[4], bsw[4];
#pragma unroll
    for (int i = 0; i < 4; i++) {
        int ra = wm + i * 16 + lrow;
        arow[i] = (uint32_t)ra * 128u; asw[i] = (uint32_t)(ra & 7);
        int rb = wn + i * 16 + lrow;
        brow[i] = (uint32_t)rb * 128u; bsw[i] = (uint32_t)(rb & 7);
    }

    float acc[4][8][4];
#pragma unroll
    for (int i = 0; i < 4; i++)
#pragma unroll
        for (int j = 0; j < 8; j++)
#pragma unroll
            for (int q = 0; q < 4; q++) acc[i][j][q] = 0.0f;

    int s = 0;
    for (int kt = 0; kt < NKT; kt++) {
        MBAR_WAIT(sbase + OFF_FULL(s), (kt / PSTG) & 1);
        uint32_t aS = sbase + OFF_A(s);
        uint32_t bS = sbase + OFF_B(s);
#pragma unroll
        for (int ks = 0; ks < 4; ks++) {
            uint32_t chunk = (uint32_t)(ks * 2 + lhi);
            uint32_t a[4][4];
            uint32_t bf[8][2];
#pragma unroll
            for (int mi = 0; mi < 4; mi++)
                ldsm_x4(a[mi][0], a[mi][1], a[mi][2], a[mi][3],
                        aS + arow[mi] + (((chunk ^ asw[mi]) & 7u) << 4));
#pragma unroll
            for (int nj = 0; nj < 4; nj++) {
                uint32_t r0, r1, r2, r3;
                ldsm_x4(r0, r1, r2, r3,
                        bS + brow[nj] + (((chunk ^ bsw[nj]) & 7u) << 4));
                bf[2*nj][0] = r0; bf[2*nj][1] = r2;
                bf[2*nj+1][0] = r1; bf[2*nj+1][1] = r3;
            }
#pragma unroll
            for (int mi = 0; mi < 4; mi++)
#pragma unroll
                for (int ni = 0; ni < 8; ni++)
                    mma16816(acc[mi][ni], a[mi], bf[ni][0], bf[ni][1]);
        }
        if (lane == 0) MBAR_ARRIVE(sbase + OFF_EMPTY(s));
        if (++s == PSTG) s = 0;
    }

    // epilogue: bias + store
    int crow = lane >> 2;
    int ccol = (lane & 3) * 2;
    float2 bfrag[8];
#pragma unroll
    for (int ni = 0; ni < 8; ni++)
        bfrag[ni] = __ldg(reinterpret_cast<const float2*>(bias + n0 + wn + ni * 8 + ccol));
#pragma unroll
    for (int mi = 0; mi < 4; mi++) {
        int m_lo = m0 + wm + mi * 16 + crow;
#pragma unroll
        for (int ni = 0; ni < 8; ni++) {
            int col = n0 + wn + ni * 8 + ccol;
            float2 v0, v1;
            v0.x = acc[mi][ni][0] + bfrag[ni].x;
            v0.y = acc[mi][ni][1] + bfrag[ni].y;
            v1.x = acc[mi][ni][2] + bfrag[ni].x;
            v1.y = acc[mi][ni][3] + bfrag[ni].y;
            *reinterpret_cast<float2*>(out + (size_t)m_lo * OUT_F + col) = v0;
            *reinterpret_cast<float2*>(out + (size_t)(m_lo + 8) * OUT_F + col) = v1;
        }
    }
}

typedef CUresult (*tmap_fn_t)(CUtensorMap*, CUtensorMapDataType, cuuint32_t, void*,
                              const cuuint64_t*, const cuuint64_t*, const cuuint32_t*,
                              const cuuint32_t*, CUtensorMapInterleave, CUtensorMapSwizzle,
                              CUtensorMapL2promotion, CUtensorMapFloatOOBfill);

static void make_map(tmap_fn_t enc, CUtensorMap* m, void* ptr,
                     uint64_t d0, uint64_t d1, uint32_t b0, uint32_t b1) {
    cuuint64_t dims[2]    = {(cuuint64_t)d0, (cuuint64_t)d1};
    cuuint64_t strides[1] = {(cuuint64_t)d0 * 2};
    cuuint32_t es[2]      = {1, 1};
    cuuint32_t box[2]     = {b0, b1};
    enc(m, CU_TENSOR_MAP_DATA_TYPE_FLOAT16, 2, ptr, dims, strides, box, es,
        CU_TENSOR_MAP_INTERLEAVE_NONE, CU_TENSOR_MAP_SWIZZLE_128B,
        CU_TENSOR_MAP_L2_PROMOTION_L2_128B, CU_TENSOR_MAP_FLOAT_OOB_FILL_NONE);
}

extern "C" void kernel_launch(void* const* d_in, const int* in_sizes, int n_in,
                              void* d_out, int out_size) {
    (void)in_sizes; (void)n_in; (void)out_size;
    const float* x      = (const float*)d_in[0];
    const float* smooth = (const float*)d_in[1];
    const float* w      = (const float*)d_in[2];
    const float* la     = (const float*)d_in[3];
    const float* lb     = (const float*)d_in[4];
    const float* bias   = (const float*)d_in[5];
    float* out = (float*)d_out;

    void *p_xcat = nullptr, *p_wcat = nullptr, *p_xs = nullptr, *p_lah = nullptr, *p_tp = nullptr;
    cudaGetSymbolAddress(&p_xcat, g_xcat);
    cudaGetSymbolAddress(&p_wcat, g_wcat);
    cudaGetSymbolAddress(&p_xs,   g_xs);
    cudaGetSymbolAddress(&p_lah,  g_lah);
    cudaGetSymbolAddress(&p_tp,   g_tp);

    build_wcat_kernel<<<(OUT_F * KTOT) / 256, 256>>>(w, lb, (__half*)p_wcat);
    build_lah_kernel<<<(RANK * IN_F) / 256, 256>>>(la, (__half*)p_lah);
    quant_x_kernel<<<(MROWS * IN_F / 16) / 128, 128>>>(x, smooth, (__half*)p_xs, (__half*)p_xcat);
    zero_tail_kernel<<<64, 256>>>((__half*)p_xcat);

    void* fnp = nullptr;
    cudaDriverEntryPointQueryResult qr;
    cudaGetDriverEntryPointByVersion("cuTensorMapEncodeTiled", &fnp, 12000,
                                     cudaEnableDefault, &qr);
    tmap_fn_t enc = (tmap_fn_t)fnp;

    CUtensorMap ta, tb, txs, tla;
    make_map(enc, &ta,  p_xcat, KTOT, MROWS, TK, TM);
    make_map(enc, &tb,  p_wcat, KTOT, OUT_F, TK, TN);
    make_map(enc, &txs, p_xs,   IN_F, MROWS, 64, 128);
    make_map(enc, &tla, p_lah,  IN_F, RANK,  64, 32);

    {
        dim3 lg(MROWS / 128, KSPLIT);
        lora_mma_kernel<<<lg, 160, L_SMEM>>>(txs, tla, (float*)p_tp);
        lora_t_reduce<<<(MROWS * RANK) / 256, 256>>>((const float*)p_tp, (__half*)p_xcat);
    }

    cudaFuncSetAttribute(gemm_kernel, cudaFuncAttributeMaxDynamicSharedMemorySize, SMEM_TOTAL);
    dim3 grid(MROWS / TM, OUT_F / TN);
    gemm_kernel<<<grid, 288, SMEM_TOTAL>>>(ta, tb, bias, out);
}